// round 10
// baseline (speedup 1.0000x reference)
#include <cuda_runtime.h>
#include <cuda_fp16.h>
#include <cstdint>

// CMPModel density matrix via fp16 mma.sync m16n8k16 (f32 accum), sm_103.
// V=50000, D=256, S=128, B=64.
//
// R[k,d]=word_emb[q[k],d], I[k,d]=cmp_emb[q[k],d]*pos[k]
//   real[d,e] = sum_k w[k]( R[k,d]R[k,e] + I[k,d]I[k,e] )
//   imag[d,e] = sum_k w[k]( I[k,d]R[k,e] - R[k,d]I[k,e] )
//
// CTA = (e-half, d-half, batch): 128x128 tile, BOTH real+imag. 512 thr,
// 16 warps, warp = 32(d) x 32(e).
// KC=64: the whole S=128 reduction is 2 chunks -> only TWO __syncthreads
// in the entire mainloop.  gather(1)'s LDGs issue before compute(0) so
// their latency hides under ~3.5K cycles of MMA.
// Fragments via ldmatrix.x4.trans from [k][feat] tiles (256B rows,
// chunk^(k&7) swizzle).  Imag minus sign: negate aR fragment (XOR).

#define D_DIM 256
#define S_LEN 128
#define B_DIM 64
#define KC    64

#define TILE_BYTES  16384                   // 64 k x 128 feat x 2B
#define STAGE_BYTES (4 * TILE_BYTES)        // AR, AI, BR, BI = 64KB
#define SMEM_BYTES  (2 * STAGE_BYTES)       // 128KB

#define AR_OFF 0
#define AI_OFF 16384
#define BR_OFF 32768
#define BI_OFF 49152

__device__ __forceinline__ void ldmx4t(uint32_t* r, uint32_t addr) {
    asm("ldmatrix.sync.aligned.m8n8.x4.trans.shared.b16 {%0,%1,%2,%3}, [%4];"
        : "=r"(r[0]), "=r"(r[1]), "=r"(r[2]), "=r"(r[3]) : "r"(addr));
}

__device__ __forceinline__ void mma16(float* c, const uint32_t* a,
                                      const uint32_t* b) {
    asm("mma.sync.aligned.m16n8k16.row.col.f32.f16.f16.f32 "
        "{%0,%1,%2,%3}, {%4,%5,%6,%7}, {%8,%9}, {%0,%1,%2,%3};"
        : "+f"(c[0]), "+f"(c[1]), "+f"(c[2]), "+f"(c[3])
        : "r"(a[0]), "r"(a[1]), "r"(a[2]), "r"(a[3]), "r"(b[0]), "r"(b[1]));
}

__device__ __forceinline__ uint32_t h2(float x, float y) {
    __half2 h = __halves2half2(__float2half_rn(x), __float2half_rn(y));
    return *reinterpret_cast<uint32_t*>(&h);
}

__global__ void __launch_bounds__(512, 1)
cmp_fp16b_kernel(const int*   __restrict__ questions,
                 const float* __restrict__ qpos,
                 const float* __restrict__ wemb,
                 const float* __restrict__ cemb,
                 const float* __restrict__ wq,
                 float*       __restrict__ out)
{
    extern __shared__ char sm[];
    __shared__ int   sq[S_LEN];
    __shared__ float sp[S_LEN];
    __shared__ float sw[S_LEN];

    const int tid  = threadIdx.x;
    const int wid  = tid >> 5;
    const int lane = tid & 31;
    const int et   = blockIdx.x;
    const int dt   = blockIdx.y;
    const int b    = blockIdx.z;

    if (tid < S_LEN) {
        sq[tid] = questions[b * S_LEN + tid];
        sp[tid] = qpos[b * S_LEN + tid];
        sw[tid] = wq[tid];
    }
    __syncthreads();

    const uint32_t smem_u = (uint32_t)__cvta_generic_to_shared(sm);

    const int mr = wid >> 2;       // d block (32 rows), 0..3
    const int nc = wid & 3;        // e block (32 cols), 0..3

    float accRe[2][4][4];
    float accIm[2][4][4];
#pragma unroll
    for (int i = 0; i < 2; i++)
#pragma unroll
        for (int j = 0; j < 4; j++)
#pragma unroll
            for (int q = 0; q < 4; q++) { accRe[i][j][q] = 0.f; accIm[i][j][q] = 0.f; }

    // ldmatrix per-lane address components
    const int xorv  = lane & 7;
    const int krowA = (lane & 7) | ((lane & 16) >> 1);   // A: m8-sel in bit3
    const int aCh   = (lane >> 3) & 1;
    const int krowB = (lane & 7) | (lane & 8);           // B: n8-sel in bit4
    const int bCh   = (lane >> 4) & 1;

    const uint32_t aBase = (uint32_t)krowA * 256 +
        (uint32_t)(((mr * 4 + aCh) ^ xorv) * 16);
    const uint32_t bBase = (uint32_t)krowB * 256 +
        (uint32_t)(((nc * 4 + bCh) ^ xorv) * 16);

    // ---- gather chunk g (64 tokens) into stage buffer g ----
    auto gather = [&](int g) {
        const uint32_t stg = smem_u + (uint32_t)g * STAGE_BYTES;
#pragma unroll 4
        for (int i = 0; i < 8; ++i) {
            const int t    = tid + i * 512;
            const int half = t >> 11;            // 0: A (d-side), 1: B (e-side)
            const int k    = (t >> 5) & 63;
            const int f4   = t & 31;
            const int fofs = (half ? et : dt) * 128 + f4 * 4;

            const int   s  = g * KC + k;
            const int   q  = sq[s];
            const float pp = sp[s];
            const float4 rv = *(const float4*)(wemb + (size_t)q * D_DIM + fofs);
            const float4 cv = *(const float4*)(cemb + (size_t)q * D_DIM + fofs);

            const uint32_t dst = stg + (half ? BR_OFF : AR_OFF) +
                (uint32_t)k * 256 +
                (uint32_t)(((f4 >> 1) ^ (k & 7)) * 16 + (f4 & 1) * 8);

            if (half == 0) {
                uint2 vR = make_uint2(h2(rv.x, rv.y), h2(rv.z, rv.w));
                uint2 vI = make_uint2(h2(cv.x * pp, cv.y * pp),
                                      h2(cv.z * pp, cv.w * pp));
                asm volatile("st.shared.v2.b32 [%0], {%1,%2};"
                             :: "r"(dst), "r"(vR.x), "r"(vR.y));
                asm volatile("st.shared.v2.b32 [%0], {%1,%2};"
                             :: "r"(dst + (AI_OFF - AR_OFF)), "r"(vI.x), "r"(vI.y));
            } else {
                const float ww = sw[s];
                const float wp = ww * pp;
                uint2 vR = make_uint2(h2(rv.x * ww, rv.y * ww),
                                      h2(rv.z * ww, rv.w * ww));
                uint2 vI = make_uint2(h2(cv.x * wp, cv.y * wp),
                                      h2(cv.z * wp, cv.w * wp));
                asm volatile("st.shared.v2.b32 [%0], {%1,%2};"
                             :: "r"(dst), "r"(vR.x), "r"(vR.y));
                asm volatile("st.shared.v2.b32 [%0], {%1,%2};"
                             :: "r"(dst + (BI_OFF - BR_OFF)), "r"(vI.x), "r"(vI.y));
            }
        }
    };

    // ---- compute one 64-token stage: 4 k16-groups ----
    auto compute = [&](int g) {
        const uint32_t stg = smem_u + (uint32_t)g * STAGE_BYTES;
#pragma unroll
        for (int kg = 0; kg < 4; ++kg) {
            const uint32_t kofs = (uint32_t)kg * 4096;   // 16 k-rows * 256B

            uint32_t bR[8], bI[8];
#pragma unroll
            for (int ntp = 0; ntp < 2; ++ntp) {
                const uint32_t badj = bBase ^ (uint32_t)(ntp * 2 * 16);
                ldmx4t(bR + 4 * ntp, stg + BR_OFF + kofs + badj);
                ldmx4t(bI + 4 * ntp, stg + BI_OFF + kofs + badj);
            }

#pragma unroll
            for (int mt = 0; mt < 2; ++mt) {
                const uint32_t aadj = aBase ^ (uint32_t)(mt * 2 * 16);
                uint32_t aR[4], aI[4], aN[4];
                ldmx4t(aR, stg + AR_OFF + kofs + aadj);
                ldmx4t(aI, stg + AI_OFF + kofs + aadj);
#pragma unroll
                for (int j = 0; j < 4; ++j) aN[j] = aR[j] ^ 0x80008000u;

#pragma unroll
                for (int nt = 0; nt < 4; ++nt) {
                    const int bi = (nt >> 1) * 4 + (nt & 1) * 2;
                    mma16(accRe[mt][nt], aR, bR + bi);
                }
#pragma unroll
                for (int nt = 0; nt < 4; ++nt) {
                    const int bi = (nt >> 1) * 4 + (nt & 1) * 2;
                    mma16(accRe[mt][nt], aI, bI + bi);
                }
#pragma unroll
                for (int nt = 0; nt < 4; ++nt) {
                    const int bi = (nt >> 1) * 4 + (nt & 1) * 2;
                    mma16(accIm[mt][nt], aI, bR + bi);
                }
#pragma unroll
                for (int nt = 0; nt < 4; ++nt) {
                    const int bi = (nt >> 1) * 4 + (nt & 1) * 2;
                    mma16(accIm[mt][nt], aN, bI + bi);
                }
            }
        }
    };

    gather(0);
    __syncthreads();
    gather(1);        // LDGs issue now; latency hides under compute(0)
    compute(0);
    __syncthreads();
    compute(1);

    // ---- epilogue ----
    const int r = lane >> 2;
    const int c = lane & 3;
    float* oRe = out + (size_t)b * D_DIM * D_DIM;
    float* oIm = oRe + (size_t)B_DIM * D_DIM * D_DIM;
#pragma unroll
    for (int mt = 0; mt < 2; ++mt) {
        const int d = dt * 128 + mr * 32 + mt * 16 + r;
#pragma unroll
        for (int nt = 0; nt < 4; ++nt) {
            const int e = et * 128 + nc * 32 + nt * 8 + 2 * c;
            *(float2*)(oRe + (size_t)d * D_DIM + e) =
                make_float2(accRe[mt][nt][0], accRe[mt][nt][1]);
            *(float2*)(oRe + (size_t)(d + 8) * D_DIM + e) =
                make_float2(accRe[mt][nt][2], accRe[mt][nt][3]);
            *(float2*)(oIm + (size_t)d * D_DIM + e) =
                make_float2(accIm[mt][nt][0], accIm[mt][nt][1]);
            *(float2*)(oIm + (size_t)(d + 8) * D_DIM + e) =
                make_float2(accIm[mt][nt][2], accIm[mt][nt][3]);
        }
    }
}

extern "C" void kernel_launch(void* const* d_in, const int* in_sizes, int n_in,
                              void* d_out, int out_size) {
    const int*   questions = (const int*)d_in[0];
    const float* qpos      = (const float*)d_in[1];
    const float* wemb      = (const float*)d_in[2];
    const float* cemb      = (const float*)d_in[3];
    const float* wq        = (const float*)d_in[4];
    float*       out       = (float*)d_out;

    cudaFuncSetAttribute(cmp_fp16b_kernel,
                         cudaFuncAttributeMaxDynamicSharedMemorySize, SMEM_BYTES);

    dim3 grid(2 /*e-half*/, 2 /*d-half*/, B_DIM);
    cmp_fp16b_kernel<<<grid, 512, SMEM_BYTES>>>(questions, qpos, wemb, cemb, wq, out);
}